// round 3
// baseline (speedup 1.0000x reference)
#include <cuda_runtime.h>
#include <math.h>

// ============================================================================
// ExponentialConcordanceLoss, O(N), single-block / all-in-shared-memory.
//
// loss = ( sum_{i,j: t[j]<t[i], e[j], finite both} exp(s[i]-s[j]) ) / max(cnt,1)
//   a[i]  = finite[i] ? exp(s[i]) : 0          (kept in registers)
//   b0[j] = (finite[j] && e[j]) ? exp(-s[j]) : 0
//   total = sum_i a[i] * (prefB0[bucket(i)] + same-bucket strict compares)
//
// Strict order via 2048 monotone buckets over [tmin,tmax] of finite t, plus
// exact same-bucket comparisons against original t (ties & any distribution
// stay correct). Counts are int32 end-to-end (max 67M < 2^31).
// Entire working set (~160 KB) lives in one SM's shared memory; all phase
// ordering is __syncthreads(). One launch, no grid barriers, no scratch DRAM.
// ============================================================================

#define NMAX     8192
#define KB       2048
#define NTHREADS 1024
#define EPT      (NMAX / NTHREADS)   // 8 elements per thread

// SMEM layout sizes (bytes)
//   t        : NMAX*4   = 32768
//   b0       : NMAX*4   = 32768
//   bk(pk)   : NMAX*2   = 16384   (bucket in bits[0:14], event flag in bit 15)
//   pos      : NMAX*2   = 16384
//   srt      : NMAX*2   = 16384
//   hCnt     : KB*4     = 8192
//   hB0      : KB*4     = 8192
//   hC0      : KB*4     = 8192
//   pB0      : KB*4     = 8192
//   pC0      : KB*4     = 8192
//   start    : KB*4     = 8192
#define SMEM_BYTES (NMAX*4*2 + NMAX*2*3 + KB*4*6)   // 163840

extern __shared__ unsigned char smem_raw[];

__global__ void __launch_bounds__(NTHREADS, 1)
fused1(const float* __restrict__ preds,
       const float* __restrict__ targets,
       float* __restrict__ out, int n) {
    float*          s_t    = (float*)smem_raw;
    float*          s_b0   = s_t + NMAX;
    unsigned short* s_bk   = (unsigned short*)(s_b0 + NMAX);
    unsigned short* s_pos  = s_bk + NMAX;
    unsigned short* s_srt  = s_pos + NMAX;
    int*            s_hCnt = (int*)(s_srt + NMAX);
    float*          s_hB0  = (float*)(s_hCnt + KB);
    int*            s_hC0  = (int*)(s_hB0 + KB);
    float*          s_pB0  = (float*)(s_hC0 + KB);
    int*            s_pC0  = (int*)(s_pB0 + KB);
    int*            s_st   = (int*)(s_pC0 + KB);

    __shared__ float sWmn[32], sWmx[32];
    __shared__ float sWsum[32];
    __shared__ int   sWcnt[32];
    __shared__ float sScale[2];                 // [0]=tmin, [1]=scale
    __shared__ float wScB[32];
    __shared__ int   wScC[32], wScN[32];

    const int tid  = threadIdx.x;
    const int lane = tid & 31;
    const int warp = tid >> 5;

    // ---- zero histograms (before first sync) -------------------------------
#pragma unroll
    for (int u = 0; u < KB / NTHREADS; u++) {
        int h = tid + u * NTHREADS;
        s_hCnt[h] = 0; s_hB0[h] = 0.0f; s_hC0[h] = 0;
    }

    // ---- Phase A: load, prep, per-warp min/max of finite t -----------------
    float a_reg[EPT];
    int   finMask = 0;
    float tmn = __int_as_float(0x7f800000);     // +inf
    float tmx = -tmn;
#pragma unroll
    for (int u = 0; u < EPT; u++) {
        int i = tid + u * NTHREADS;
        float s  = 0.0f;
        float tv = __int_as_float(0x7fc00000);  // qNaN
        float ev = 0.0f;
        if (i < n) {
            s = preds[i];
            float2 tg = ((const float2*)targets)[i];
            tv = tg.x; ev = tg.y;
        }
        bool fin = (i < n) && isfinite(tv) && isfinite(s);
        bool e   = fin && (ev != 0.0f);
        s_t[i < NMAX ? i : 0]  = tv;            // i<NMAX always; keeps compiler honest
        s_b0[i < NMAX ? i : 0] = e ? __expf(-s) : 0.0f;
        a_reg[u] = fin ? __expf(s) : 0.0f;
        if (fin) { finMask |= (1 << u); tmn = fminf(tmn, tv); tmx = fmaxf(tmx, tv); }
        // stash event flag temporarily in bk (bucket filled in phase B)
        s_bk[i < NMAX ? i : 0] = e ? 0x8000u : 0u;
    }
#pragma unroll
    for (int o = 16; o > 0; o >>= 1) {
        tmn = fminf(tmn, __shfl_xor_sync(0xffffffffu, tmn, o));
        tmx = fmaxf(tmx, __shfl_xor_sync(0xffffffffu, tmx, o));
    }
    if (lane == 0) { sWmn[warp] = tmn; sWmx[warp] = tmx; }
    __syncthreads();

    if (warp == 0) {
        float a = sWmn[lane], b = sWmx[lane];
#pragma unroll
        for (int o = 16; o > 0; o >>= 1) {
            a = fminf(a, __shfl_xor_sync(0xffffffffu, a, o));
            b = fmaxf(b, __shfl_xor_sync(0xffffffffu, b, o));
        }
        if (lane == 0) {
            float range = b - a;
            sScale[0] = a;
            sScale[1] = (range > 0.0f) ? ((float)KB / range) : 0.0f;
        }
    }
    __syncthreads();

    // ---- Phase B: bucket + histogram (smem atomics) ------------------------
    {
        float tmin  = sScale[0];
        float scale = sScale[1];
#pragma unroll
        for (int u = 0; u < EPT; u++) {
            int i = tid + u * NTHREADS;
            if (i < n) {
                float tv = s_t[i];
                float x  = (tv - tmin) * scale;     // NaN -> 0 after cvt
                int bkt = (int)x;
                bkt = max(0, min(KB - 1, bkt));
                unsigned short eflag = s_bk[i];     // 0x8000 if event
                s_bk[i]  = (unsigned short)(bkt | eflag);
                s_pos[i] = (unsigned short)atomicAdd(&s_hCnt[bkt], 1);
                atomicAdd(&s_hB0[bkt], s_b0[i]);
                if (eflag) atomicAdd(&s_hC0[bkt], 1);
            }
        }
    }
    __syncthreads();

    // ---- Phase C: 3-way exclusive scan over KB buckets (2 per thread) ------
    {
        int base = tid * 2;
        float hb0 = s_hB0[base], hb1 = s_hB0[base + 1];
        int   hc0 = s_hC0[base], hc1 = s_hC0[base + 1];
        int   hn0 = s_hCnt[base], hn1 = s_hCnt[base + 1];

        float rb = hb0 + hb1;  int rc = hc0 + hc1;  int rn = hn0 + hn1;
        float Tb = rb;         int Tc = rc;         int Tn = rn;
#pragma unroll
        for (int o = 1; o < 32; o <<= 1) {
            float vb = __shfl_up_sync(0xffffffffu, rb, o);
            int   vc = __shfl_up_sync(0xffffffffu, rc, o);
            int   vn = __shfl_up_sync(0xffffffffu, rn, o);
            if (lane >= o) { rb += vb; rc += vc; rn += vn; }
        }
        if (lane == 31) { wScB[warp] = rb; wScC[warp] = rc; wScN[warp] = rn; }
        __syncthreads();
        float ob = 0.0f; int oc = 0, on = 0;
        for (int w = 0; w < warp; w++) { ob += wScB[w]; oc += wScC[w]; on += wScN[w]; }
        float eb = ob + rb - Tb;        // exclusive prefix for this thread
        int   ec = oc + rc - Tc;
        int   en = on + rn - Tn;

        s_pB0[base]     = eb;        s_pB0[base + 1] = eb + hb0;
        s_pC0[base]     = ec;        s_pC0[base + 1] = ec + hc0;
        s_st[base]      = en;        s_st[base + 1]  = en + hn0;
    }
    __syncthreads();

    // ---- Phase D: scatter into bucket-sorted order -------------------------
#pragma unroll
    for (int u = 0; u < EPT; u++) {
        int i = tid + u * NTHREADS;
        if (i < n) {
            int bkt = s_bk[i] & 0x7FFF;
            s_srt[s_st[bkt] + s_pos[i]] = (unsigned short)i;
        }
    }
    __syncthreads();

    // ---- Phase E: per-element sums -----------------------------------------
    float ts = 0.0f;
    int   tc = 0;
#pragma unroll
    for (int u = 0; u < EPT; u++) {
        int i = tid + u * NTHREADS;
        if (i < n) {
            unsigned pk = s_bk[i];
            int   k   = pk & 0x7FFF;
            float S   = s_pB0[k];
            int   C   = s_pC0[k];
            int   st  = s_st[k];
            int   cnt = s_hCnt[k];
            float ti  = s_t[i];
            for (int m = st; m < st + cnt; m++) {
                int   j  = s_srt[m];
                float tj = s_t[j];
                if (tj < ti) {                    // strict: excludes self & ties
                    S += s_b0[j];
                    C += (s_bk[j] >> 15);
                }
            }
            ts += a_reg[u] * S;
            if (finMask & (1 << u)) tc += C;
        }
    }

    // ---- final reduction ----------------------------------------------------
#pragma unroll
    for (int o = 16; o > 0; o >>= 1) {
        ts += __shfl_xor_sync(0xffffffffu, ts, o);
        tc += __shfl_xor_sync(0xffffffffu, tc, o);
    }
    if (lane == 0) { sWsum[warp] = ts; sWcnt[warp] = tc; }
    __syncthreads();
    if (warp == 0) {
        float s = sWsum[lane];
        int   c = sWcnt[lane];
#pragma unroll
        for (int o = 16; o > 0; o >>= 1) {
            s += __shfl_xor_sync(0xffffffffu, s, o);
            c += __shfl_xor_sync(0xffffffffu, c, o);
        }
        if (lane == 0) out[0] = s / fmaxf((float)c, 1.0f);
    }
}

// ---------------------------------------------------------------------------
extern "C" void kernel_launch(void* const* d_in, const int* in_sizes, int n_in,
                              void* d_out, int out_size) {
    const float* preds   = (const float*)d_in[0];
    const float* targets = (const float*)d_in[1];
    int n = in_sizes[0];
    if (n > NMAX) n = NMAX;

    // Idempotent attribute set (required for >48KB dynamic smem); not a
    // stream-ordered op, so safe under graph capture.
    cudaFuncSetAttribute(fused1, cudaFuncAttributeMaxDynamicSharedMemorySize,
                         SMEM_BYTES);

    fused1<<<1, NTHREADS, SMEM_BYTES>>>(preds, targets, (float*)d_out, n);
}

// round 4
// speedup vs baseline: 1.9227x; 1.9227x over previous
#include <cuda_runtime.h>
#include <math.h>

// ============================================================================
// ExponentialConcordanceLoss, O(N), 8-CTA cluster (1 element / thread).
//
// loss = ( sum_{i,j: t[j]<t[i], e[j], finite both} exp(s[i]-s[j]) ) / max(cnt,1)
//   a[i]  = finite[i] ? exp(s[i]) : 0
//   b0[j] = (finite[j] && e[j]) ? exp(-s[j]) : 0     (events only matter)
//   total = sum_i a[i] * ( prefB0[bucket(i)] + same-bucket strict compares )
//   count = sum_{finite i} ( prefEvtCnt[bucket(i)] + same-bucket strict count )
//
// Strict order via 2048 monotone buckets over [tmin,tmax] of finite t plus
// exact same-bucket comparisons (handles ties / any distribution).
// ONLY events are histogrammed and scattered; the scattered record is the
// (t_j, b0_j) pair itself, so phase E does one 8B load per candidate.
// Bucket scan is recomputed per-CTA into local SMEM (kills one sync).
// Phase ordering across CTAs: cluster.sync (~380cyc, flushes L1D).
// Counts are int32 end-to-end (max 8192*8192 < 2^31).
// ============================================================================

#define NMAX     8192
#define KB       2048
#define NCTAS    8
#define NTHREADS 1024

__device__ int    g_histCnt[KB];
__device__ float  g_histB0[KB];
__device__ float2 g_srec[NMAX];          // bucket-sorted (t, b0) of events
__device__ float  g_blkMin[NCTAS];
__device__ float  g_blkMax[NCTAS];
__device__ float  g_blockSum[NCTAS];
__device__ int    g_blockCnt[NCTAS];

__device__ __forceinline__ void cluster_sync_fenced() {
    __threadfence();                                       // order global stores
    asm volatile("barrier.cluster.arrive.aligned;" ::: "memory");
    asm volatile("barrier.cluster.wait.aligned;"   ::: "memory");
}

__global__ void __launch_bounds__(NTHREADS, 1) __cluster_dims__(NCTAS, 1, 1)
fused_cluster(const float* __restrict__ preds,
              const float* __restrict__ targets,
              float* __restrict__ out, int n) {
    __shared__ float sWmn[32], sWmx[32];
    __shared__ float sWsum[32];
    __shared__ int   sWcnt[32];
    __shared__ float s_pB0[KB];          // exclusive prefix of event b0
    __shared__ int   s_st[KB + 1];       // exclusive prefix of event counts
    __shared__ float sScanB[33];
    __shared__ int   sScanN[33];

    const int tid  = threadIdx.x;
    const int cta  = blockIdx.x;
    const int i    = cta * NTHREADS + tid;
    const int lane = tid & 31;
    const int warp = tid >> 5;

    // ---- Phase A: load + per-element prep + CTA min/max; zero hist ---------
    if (i < KB) { g_histCnt[i] = 0; g_histB0[i] = 0.0f; }

    float tv = 0.0f, b0 = 0.0f, a = 0.0f;
    bool  fin = false, e = false;
    if (i < n) {
        float  s  = preds[i];
        float2 tg = ((const float2*)targets)[i];
        tv = tg.x;
        fin = isfinite(tv) && isfinite(s);
        e   = fin && (tg.y != 0.0f);
        b0  = e   ? __expf(-s) : 0.0f;
        a   = fin ? __expf(s)  : 0.0f;
    }

    float tmn = fin ? tv : __int_as_float(0x7f800000);     // +inf
    float tmx = fin ? tv : __int_as_float(0xff800000);     // -inf
#pragma unroll
    for (int o = 16; o > 0; o >>= 1) {
        tmn = fminf(tmn, __shfl_xor_sync(0xffffffffu, tmn, o));
        tmx = fmaxf(tmx, __shfl_xor_sync(0xffffffffu, tmx, o));
    }
    if (lane == 0) { sWmn[warp] = tmn; sWmx[warp] = tmx; }
    __syncthreads();
    if (tid == 0) {
        float mn = sWmn[0], mx = sWmx[0];
#pragma unroll
        for (int w = 1; w < 32; w++) { mn = fminf(mn, sWmn[w]); mx = fmaxf(mx, sWmx[w]); }
        g_blkMin[cta] = mn; g_blkMax[cta] = mx;
    }
    cluster_sync_fenced();                                 // sync 1

    // ---- Phase B: global min/max (broadcast reads) + event histogram -------
    float gmn = __int_as_float(0x7f800000);
    float gmx = __int_as_float(0xff800000);
#pragma unroll
    for (int b = 0; b < NCTAS; b++) {
        gmn = fminf(gmn, __ldcg(&g_blkMin[b]));
        gmx = fmaxf(gmx, __ldcg(&g_blkMax[b]));
    }
    float range = gmx - gmn;
    float scale = (range > 0.0f) ? ((float)KB / range) : 0.0f;

    int bkt = 0, pos = 0;
    if (fin) {
        float x = (tv - gmn) * scale;
        bkt = (int)x;
        bkt = max(0, min(KB - 1, bkt));
    }
    if (e) {
        pos = atomicAdd(&g_histCnt[bkt], 1);
        atomicAdd(&g_histB0[bkt], b0);
    }
    cluster_sync_fenced();                                 // sync 2

    // ---- Phase C: per-CTA local 2-way exclusive scan (2 buckets/thread) ----
    {
        int   base = tid * 2;
        float hb0 = __ldcg(&g_histB0[base]), hb1 = __ldcg(&g_histB0[base + 1]);
        int   hn0 = __ldcg(&g_histCnt[base]), hn1 = __ldcg(&g_histCnt[base + 1]);

        float rb = hb0 + hb1;  int rn = hn0 + hn1;
        float Tb = rb;         int Tn = rn;
#pragma unroll
        for (int o = 1; o < 32; o <<= 1) {
            float vb = __shfl_up_sync(0xffffffffu, rb, o);
            int   vn = __shfl_up_sync(0xffffffffu, rn, o);
            if (lane >= o) { rb += vb; rn += vn; }
        }
        if (lane == 31) { sScanB[warp] = rb; sScanN[warp] = rn; }
        __syncthreads();
        if (warp == 0) {                                   // scan 32 warp totals
            float wb = sScanB[lane]; int wn = sScanN[lane];
#pragma unroll
            for (int o = 1; o < 32; o <<= 1) {
                float vb = __shfl_up_sync(0xffffffffu, wb, o);
                int   vn = __shfl_up_sync(0xffffffffu, wn, o);
                if (lane >= o) { wb += vb; wn += vn; }
            }
            sScanB[lane + 1] = wb; sScanN[lane + 1] = wn;  // inclusive -> +1
            if (lane == 0) { sScanB[0] = 0.0f; sScanN[0] = 0; }
        }
        __syncthreads();
        float eb = sScanB[warp] + rb - Tb;                 // thread-exclusive
        int   en = sScanN[warp] + rn - Tn;
        s_pB0[base]     = eb;  s_pB0[base + 1] = eb + hb0;
        s_st[base]      = en;  s_st[base + 1]  = en + hn0;
        if (tid == NTHREADS - 1) s_st[KB] = en + rn - (rn - Tn); // = en + Tn
    }
    __syncthreads();

    // ---- Phase D: scatter event records into bucket-sorted order -----------
    if (e) g_srec[s_st[bkt] + pos] = make_float2(tv, b0);
    cluster_sync_fenced();                                 // sync 3

    // ---- Phase E: per-element sums -----------------------------------------
    float ts = 0.0f;
    int   tc = 0;
    if (fin) {
        float S   = s_pB0[bkt];
        int   C   = s_st[bkt];
        int   st  = C;                 // same thing: event-count prefix
        int   cnt = s_st[bkt + 1] - st;
        for (int m = st; m < st + cnt; m++) {
            float2 rec;
            asm volatile("ld.global.cg.v2.f32 {%0,%1}, [%2];"
                         : "=f"(rec.x), "=f"(rec.y) : "l"(&g_srec[m]));
            if (rec.x < tv) { S += rec.y; C += 1; }        // strict: drops ties/self
        }
        ts = a * S;
        tc = C;
    }

    // ---- CTA reduction ------------------------------------------------------
#pragma unroll
    for (int o = 16; o > 0; o >>= 1) {
        ts += __shfl_xor_sync(0xffffffffu, ts, o);
        tc += __shfl_xor_sync(0xffffffffu, tc, o);
    }
    if (lane == 0) { sWsum[warp] = ts; sWcnt[warp] = tc; }
    __syncthreads();
    if (warp == 0) {
        float s = sWsum[lane];
        int   c = sWcnt[lane];
#pragma unroll
        for (int o = 16; o > 0; o >>= 1) {
            s += __shfl_xor_sync(0xffffffffu, s, o);
            c += __shfl_xor_sync(0xffffffffu, c, o);
        }
        if (lane == 0) { g_blockSum[cta] = s; g_blockCnt[cta] = c; }
    }
    cluster_sync_fenced();                                 // sync 4

    // ---- Final: CTA 0 reduces 8 partials (deterministic order) -------------
    if (cta == 0 && tid == 0) {
        float s = 0.0f; long long c = 0;
#pragma unroll
        for (int b = 0; b < NCTAS; b++) {
            s += __ldcg(&g_blockSum[b]);
            c += (long long)__ldcg(&g_blockCnt[b]);
        }
        out[0] = s / fmaxf((float)c, 1.0f);
    }
}

// ---------------------------------------------------------------------------
extern "C" void kernel_launch(void* const* d_in, const int* in_sizes, int n_in,
                              void* d_out, int out_size) {
    const float* preds   = (const float*)d_in[0];
    const float* targets = (const float*)d_in[1];
    int n = in_sizes[0];
    if (n > NMAX) n = NMAX;
    fused_cluster<<<NCTAS, NTHREADS>>>(preds, targets, (float*)d_out, n);
}

// round 5
// speedup vs baseline: 1.9779x; 1.0287x over previous
#include <cuda_runtime.h>
#include <math.h>

// ============================================================================
// ExponentialConcordanceLoss, O(N), 8-CTA cluster, TWO cluster syncs total.
//
// loss = ( sum_{i,j: t[j]<t[i], e[j], finite both} exp(s[i]-s[j]) ) / max(cnt,1)
//   a[i]  = finite[i] ? exp(s[i]) : 0
//   b0[j] = (finite[j] && e[j]) ? exp(-s[j]) : 0
//   total = sum_i a[i] * ( prefB0[bucket(i)] + same-bucket strict compares )
//
// Key structure (per graph replay):
//   A: every CTA redundantly reads ALL preds/targets and computes the global
//      min/max of finite t itself (bitwise identical in all CTAs -> no sync,
//      no communication). Each thread keeps its own element (u == cta).
//   B: event-only histogram into GLOBAL hist (zero-invariant: the previous
//      replay re-zeroed it in phase E; zero at module load for the first run).
//   --- cluster.sync #1 ---
//   C: per-CTA local exclusive scan of 1024 buckets into SMEM (1 bkt/thread).
//   D: scatter event records (t_j, b0_j) into bucket-sorted g_srec.
//   --- cluster.sync #2 ---
//   E: per-element gather (prefix + short exact same-bucket loop, strict <,
//      so ties/self are excluded), re-zero histogram for next replay,
//      block reduce, write partial.
//   F: ticket: LAST block reduces the 8 partials in fixed order
//      (deterministic), writes out, resets ticket.
// Counts are int32 end-to-end (max 8192^2 < 2^31).
// ============================================================================

#define NMAX     8192
#define KB       1024
#define NCTAS    8
#define NTHREADS 1024

__device__ int      g_histCnt[KB];     // zero-init at load; re-zeroed each run
__device__ float    g_histB0[KB];
__device__ float2   g_srec[NMAX];      // bucket-sorted (t, b0) of events
__device__ float    g_blockSum[NCTAS];
__device__ int      g_blockCnt[NCTAS];
__device__ unsigned g_ticket;          // zero-init; reset by last block

__device__ __forceinline__ void cluster_sync_fenced() {
    __threadfence();
    asm volatile("barrier.cluster.arrive.aligned;" ::: "memory");
    asm volatile("barrier.cluster.wait.aligned;"   ::: "memory");
}

__global__ void __launch_bounds__(NTHREADS, 1) __cluster_dims__(NCTAS, 1, 1)
fused_cluster2(const float* __restrict__ preds,
               const float* __restrict__ targets,
               float* __restrict__ out, int n) {
    __shared__ float sWmn[32], sWmx[32];
    __shared__ float sWsum[32];
    __shared__ int   sWcnt[32];
    __shared__ float sScale[2];          // [0]=tmin, [1]=scale
    __shared__ float s_pB0[KB];          // exclusive prefix of event b0
    __shared__ int   s_st[KB + 1];       // exclusive prefix of event counts
    __shared__ float sScanB[33];
    __shared__ int   sScanN[33];

    const int tid  = threadIdx.x;
    const int cta  = blockIdx.x;
    const int lane = tid & 31;
    const int warp = tid >> 5;

    // ---- Phase A: redundant full read -> global min/max; keep own element --
    float my_s = 0.0f, my_t = 0.0f, my_ev = 0.0f;
    float tmn = __int_as_float(0x7f800000);     // +inf
    float tmx = __int_as_float(0xff800000);     // -inf
#pragma unroll
    for (int u = 0; u < NCTAS; u++) {
        int idx = u * NTHREADS + tid;
        float  sv = 0.0f;
        float2 tg = make_float2(__int_as_float(0x7fc00000), 0.0f);
        if (idx < n) {
            sv = preds[idx];
            tg = ((const float2*)targets)[idx];
        }
        if (isfinite(tg.x) && isfinite(sv)) {
            tmn = fminf(tmn, tg.x);
            tmx = fmaxf(tmx, tg.x);
        }
        if (u == cta) { my_s = sv; my_t = tg.x; my_ev = tg.y; }
    }
#pragma unroll
    for (int o = 16; o > 0; o >>= 1) {
        tmn = fminf(tmn, __shfl_xor_sync(0xffffffffu, tmn, o));
        tmx = fmaxf(tmx, __shfl_xor_sync(0xffffffffu, tmx, o));
    }
    if (lane == 0) { sWmn[warp] = tmn; sWmx[warp] = tmx; }
    __syncthreads();
    if (warp == 0) {
        float a2 = sWmn[lane], b2 = sWmx[lane];
#pragma unroll
        for (int o = 16; o > 0; o >>= 1) {
            a2 = fminf(a2, __shfl_xor_sync(0xffffffffu, a2, o));
            b2 = fmaxf(b2, __shfl_xor_sync(0xffffffffu, b2, o));
        }
        if (lane == 0) {
            float range = b2 - a2;
            sScale[0] = a2;
            sScale[1] = (range > 0.0f) ? ((float)KB / range) : 0.0f;
        }
    }
    __syncthreads();

    // ---- Phase B: per-element prep + event-only global histogram ------------
    const int i = cta * NTHREADS + tid;
    bool fin = (i < n) && isfinite(my_t) && isfinite(my_s);
    bool e   = fin && (my_ev != 0.0f);
    float b0 = e   ? __expf(-my_s) : 0.0f;
    float a  = fin ? __expf(my_s)  : 0.0f;

    int bkt = 0, pos = 0;
    if (fin) {
        float x = (my_t - sScale[0]) * sScale[1];
        bkt = (int)x;
        bkt = max(0, min(KB - 1, bkt));
    }
    if (e) {
        pos = atomicAdd(&g_histCnt[bkt], 1);
        atomicAdd(&g_histB0[bkt], b0);
    }
    cluster_sync_fenced();                                 // sync 1

    // ---- Phase C: per-CTA local exclusive scan (1 bucket / thread) ----------
    float hb = __ldcg(&g_histB0[tid]);
    int   hn = __ldcg(&g_histCnt[tid]);
    {
        float rb = hb; int rn = hn;
#pragma unroll
        for (int o = 1; o < 32; o <<= 1) {
            float vb = __shfl_up_sync(0xffffffffu, rb, o);
            int   vn = __shfl_up_sync(0xffffffffu, rn, o);
            if (lane >= o) { rb += vb; rn += vn; }
        }
        if (lane == 31) { sScanB[warp] = rb; sScanN[warp] = rn; }
        __syncthreads();
        if (warp == 0) {
            float wb = sScanB[lane]; int wn = sScanN[lane];
#pragma unroll
            for (int o = 1; o < 32; o <<= 1) {
                float vb = __shfl_up_sync(0xffffffffu, wb, o);
                int   vn = __shfl_up_sync(0xffffffffu, wn, o);
                if (lane >= o) { wb += vb; wn += vn; }
            }
            sScanB[lane + 1] = wb; sScanN[lane + 1] = wn;
            if (lane == 0) { sScanB[0] = 0.0f; sScanN[0] = 0; }
        }
        __syncthreads();
        float ib = sScanB[warp] + rb;                      // inclusive
        int   in2 = sScanN[warp] + rn;
        s_pB0[tid] = ib - hb;                              // exclusive
        s_st[tid]  = in2 - hn;
        if (tid == KB - 1) s_st[KB] = in2;
    }
    __syncthreads();

    // ---- Phase D: scatter event records into bucket-sorted order ------------
    if (e) g_srec[s_st[bkt] + pos] = make_float2(my_t, b0);
    cluster_sync_fenced();                                 // sync 2

    // ---- Phase E: gather + re-zero histogram for next replay ----------------
    if (tid < KB / NCTAS) {                                // 128 buckets per CTA
        int h = cta * (KB / NCTAS) + tid;
        g_histCnt[h] = 0;
        g_histB0[h]  = 0.0f;
    }

    float ts = 0.0f;
    int   tc = 0;
    if (fin) {
        float S  = s_pB0[bkt];
        int   st = s_st[bkt];
        int   en = s_st[bkt + 1];
        int   C  = st;
        for (int m = st; m < en; m++) {
            float2 rec;
            asm volatile("ld.global.cg.v2.f32 {%0,%1}, [%2];"
                         : "=f"(rec.x), "=f"(rec.y) : "l"(&g_srec[m]));
            if (rec.x < my_t) { S += rec.y; C += 1; }      // strict: drops ties/self
        }
        ts = a * S;
        tc = C;
    }

    // ---- block reduce -------------------------------------------------------
#pragma unroll
    for (int o = 16; o > 0; o >>= 1) {
        ts += __shfl_xor_sync(0xffffffffu, ts, o);
        tc += __shfl_xor_sync(0xffffffffu, tc, o);
    }
    if (lane == 0) { sWsum[warp] = ts; sWcnt[warp] = tc; }
    __syncthreads();
    if (warp == 0) {
        float s2 = sWsum[lane];
        int   c2 = sWcnt[lane];
#pragma unroll
        for (int o = 16; o > 0; o >>= 1) {
            s2 += __shfl_xor_sync(0xffffffffu, s2, o);
            c2 += __shfl_xor_sync(0xffffffffu, c2, o);
        }
        if (lane == 0) { g_blockSum[cta] = s2; g_blockCnt[cta] = c2; }
    }
    __syncthreads();

    // ---- Phase F: ticket-based final reduce (last block, fixed order) -------
    if (tid == 0) {
        __threadfence();
        unsigned tkt = atomicAdd(&g_ticket, 1u);
        if (tkt == NCTAS - 1) {
            __threadfence();
            float     s3 = 0.0f;
            long long c3 = 0;
#pragma unroll
            for (int b = 0; b < NCTAS; b++) {
                s3 += __ldcg(&g_blockSum[b]);
                c3 += (long long)__ldcg(&g_blockCnt[b]);
            }
            out[0] = s3 / fmaxf((float)c3, 1.0f);
            atomicExch(&g_ticket, 0u);                     // reset for next replay
        }
    }
}

// ---------------------------------------------------------------------------
extern "C" void kernel_launch(void* const* d_in, const int* in_sizes, int n_in,
                              void* d_out, int out_size) {
    const float* preds   = (const float*)d_in[0];
    const float* targets = (const float*)d_in[1];
    int n = in_sizes[0];
    if (n > NMAX) n = NMAX;
    fused_cluster2<<<NCTAS, NTHREADS>>>(preds, targets, (float*)d_out, n);
}